// round 11
// baseline (speedup 1.0000x reference)
#include <cuda_runtime.h>
#include <cuda_bf16.h>
#include <cstdint>
#include <math.h>

// Shapes: input [4096,32,8,8] f32 | edge_sources [32768] i32 | e [32768,32,8,8] f32
//         w_* [32,32,3,3] f32 | out [32768,32,8,8] f32
#define TILE   2048
#define NNODES 4096
__device__ float g_th[(size_t)NNODES * TILE];

typedef uint32_t u32;
typedef unsigned short u16;

// ---- smem u32-offsets ----
// A: [tap9][co32][24 slots] u32; slot = ks*8 + quad*2 + hh holds ciPair (ks*8+quad+4*hh)
#define AH_U   0u
#define AL_U   6912u          // 9*32*24
// B per item: hi [100 pix][24 slots] + lo: 4800 u32
#define B_U    13824u
#define B_ITEM 4800u
#define SMEM_BYTES ((13824u + 8u * 4800u) * 4u)   // 208896 B

#define MMA(dd, A0, A1, A2, A3, B0, B1)                                          \
    asm volatile("mma.sync.aligned.m16n8k16.row.col.f32.bf16.bf16.f32 "          \
                 "{%0,%1,%2,%3}, {%4,%5,%6,%7}, {%8,%9}, {%0,%1,%2,%3};"         \
                 : "+f"((dd)[0]), "+f"((dd)[1]), "+f"((dd)[2]), "+f"((dd)[3])    \
                 : "r"(A0), "r"(A1), "r"(A2), "r"(A3), "r"(B0), "r"(B1))

__device__ __forceinline__ float elu1(float v) { return v > 0.0f ? v : expm1f(v); }

__device__ __forceinline__ void split_bf16(float v, u16& h, u16& l) {
    __nv_bfloat16 hb = __float2bfloat16(v);
    __nv_bfloat16 lb = __float2bfloat16(v - __bfloat162float(hb));
    h = __bfloat16_as_ushort(hb);
    l = __bfloat16_as_ushort(lb);
}

// Warp-pair per item: warp computes all 32 co x 32 pixels (its y-half).
// 3-pass bf16 hi/lo split (drop lo*lo). LDS.64 fragment loads, stride-24 layout.
// MMA issue order: pass-outer / n-inner -> same-accumulator reuse distance = 8.
template <bool EDGE>
__global__ __launch_bounds__(512, 1)
void mma_conv(const float* __restrict__ x,     // [N,32,8,8]
              const float* __restrict__ w,     // [32,32,3,3]
              const int*   __restrict__ srcs,  // [E] (EDGE only)
              float*       __restrict__ out,
              int nitems)
{
    extern __shared__ __align__(16) u32 S[];
    const int tid  = threadIdx.x;
    const int wid  = tid >> 5;
    const int lane = tid & 31;
    const int row  = lane >> 2;
    const int quad = lane & 3;
    const int pr   = wid >> 1;     // pair id 0..7
    const int nh   = wid & 1;      // y-half

    // ---- one-time: weights -> A hi/lo (paired-slot layout) ----
    for (int i = tid; i < 9216; i += 512) {
        int co = i / 288, r = i - co * 288;
        int ci = r / 9,   tap = r - ci * 9;
        u16 h, l;
        split_bf16(w[i], h, l);
        int j = ci >> 1, odd = ci & 1;
        int ks = j >> 3, jq = j & 7, q = jq & 3, hh = jq >> 2;
        u32 idx = (u32)(tap * 32 + co) * 24 + ks * 8 + q * 2 + hh;
        *(u16*)((char*)S + (size_t)(AH_U + idx) * 4 + odd * 2) = h;
        *(u16*)((char*)S + (size_t)(AL_U + idx) * 4 + odd * 2) = l;
    }
    // ---- one-time: zero B region (borders stay zero) ----
    for (u32 i = tid; i < 8 * B_ITEM; i += 512) S[B_U + i] = 0;
    __syncthreads();

    u32* Bh = S + B_U + (u32)pr * B_ITEM;
    u32* Bl = Bh + 2400;
    const int t2  = tid & 63;                                   // pixel within item
    const int p24 = (((t2 >> 3) + 1) * 10 + (t2 & 7) + 1) * 24; // interior pix * 24

    for (int item = blockIdx.x * 8 + pr; item < nitems; item += gridDim.x * 8) {
        // ---- B fill: this thread's pixel, 16 ciPairs hi+lo ----
        const float* ei = x + (size_t)item * TILE;
        #pragma unroll
        for (int j = 0; j < 16; j++) {
            float v0 = __ldg(ei + (2 * j) * 64 + t2);
            float v1 = __ldg(ei + (2 * j + 1) * 64 + t2);
            u16 h0, l0, h1, l1;
            split_bf16(v0, h0, l0);
            split_bf16(v1, h1, l1);
            int ks = j >> 3, jq = j & 7, q = jq & 3, hh = jq >> 2;
            int slot = ks * 8 + q * 2 + hh;
            Bh[p24 + slot] = ((u32)h1 << 16) | h0;
            Bl[p24 + slot] = ((u32)l1 << 16) | l0;
        }
        asm volatile("bar.sync %0, 64;" :: "r"(pr + 1) : "memory");

        float d[2][4][4];
        #pragma unroll
        for (int m = 0; m < 2; m++)
            #pragma unroll
            for (int n = 0; n < 4; n++)
                #pragma unroll
                for (int k = 0; k < 4; k++) d[m][n][k] = 0.0f;

        #pragma unroll 1
        for (int tap = 0; tap < 9; tap++) {
            const int dy = tap / 3, dx = tap - dy * 3;
            const u32 pixb = (u32)(dy * 10 + dx + row + nh * 40) * 24;
            #pragma unroll
            for (int ks = 0; ks < 2; ks++) {
                const u32* ap = S + AH_U + (u32)tap * 768 + (u32)row * 24 + ks * 8 + quad * 2;
                uint2 h01 = *(const uint2*)(ap);
                uint2 h23 = *(const uint2*)(ap + 192);
                uint2 h45 = *(const uint2*)(ap + 384);
                uint2 h67 = *(const uint2*)(ap + 576);
                const u32* alp = ap + AL_U;
                uint2 l01 = *(const uint2*)(alp);
                uint2 l23 = *(const uint2*)(alp + 192);
                uint2 l45 = *(const uint2*)(alp + 384);
                uint2 l67 = *(const uint2*)(alp + 576);
                const u32* bp = Bh + pixb + ks * 8 + quad * 2;
                uint2 bh[4], bl[4];
                #pragma unroll
                for (int n = 0; n < 4; n++) {
                    bh[n] = *(const uint2*)(bp + n * 240);
                    bl[n] = *(const uint2*)(bp + n * 240 + 2400);
                }
                // pass 1: wh * eh   (8 independent accumulators)
                #pragma unroll
                for (int n = 0; n < 4; n++) {
                    MMA(d[0][n], h01.x, h23.x, h01.y, h23.y, bh[n].x, bh[n].y);
                    MMA(d[1][n], h45.x, h67.x, h45.y, h67.y, bh[n].x, bh[n].y);
                }
                // pass 2: wh * el
                #pragma unroll
                for (int n = 0; n < 4; n++) {
                    MMA(d[0][n], h01.x, h23.x, h01.y, h23.y, bl[n].x, bl[n].y);
                    MMA(d[1][n], h45.x, h67.x, h45.y, h67.y, bl[n].x, bl[n].y);
                }
                // pass 3: wl * eh
                #pragma unroll
                for (int n = 0; n < 4; n++) {
                    MMA(d[0][n], l01.x, l23.x, l01.y, l23.y, bh[n].x, bh[n].y);
                    MMA(d[1][n], l45.x, l67.x, l45.y, l67.y, bh[n].x, bh[n].y);
                }
            }
        }

        // ---- epilogue: co = m*16+row (+8), y = nh*4+n, x = 2quad..+1 ----
        if (EDGE) {
            const int src = __ldg(srcs + item);
            const float* thp = g_th + (size_t)src * TILE;
            float* op = out + (size_t)item * TILE;
            #pragma unroll
            for (int m = 0; m < 2; m++) {
                const int co0 = m * 16 + row, co1 = co0 + 8;
                #pragma unroll
                for (int n = 0; n < 4; n++) {
                    const int pb = (nh * 4 + n) * 8 + 2 * quad;
                    float2 t0 = *(const float2*)(thp + co0 * 64 + pb);
                    float2 t1 = *(const float2*)(thp + co1 * 64 + pb);
                    *(float2*)(op + co0 * 64 + pb) =
                        make_float2(elu1(t0.x * d[m][n][0]), elu1(t0.y * d[m][n][1]));
                    *(float2*)(op + co1 * 64 + pb) =
                        make_float2(elu1(t1.x * d[m][n][2]), elu1(t1.y * d[m][n][3]));
                }
            }
        } else {
            float* op = g_th + (size_t)item * TILE;
            #pragma unroll
            for (int m = 0; m < 2; m++) {
                const int co0 = m * 16 + row, co1 = co0 + 8;
                #pragma unroll
                for (int n = 0; n < 4; n++) {
                    const int pb = (nh * 4 + n) * 8 + 2 * quad;
                    *(float2*)(op + co0 * 64 + pb) = make_float2(d[m][n][0], d[m][n][1]);
                    *(float2*)(op + co1 * 64 + pb) = make_float2(d[m][n][2], d[m][n][3]);
                }
            }
        }
        asm volatile("bar.sync %0, 64;" :: "r"(pr + 1) : "memory");
    }
}

extern "C" void kernel_launch(void* const* d_in, const int* in_sizes, int n_in,
                              void* d_out, int out_size)
{
    const float* input  = (const float*)d_in[0];
    const int*   srcs   = (const int*)  d_in[1];
    const float* e      = (const float*)d_in[2];
    const float* w_node = (const float*)d_in[3];
    const float* w_edge = (const float*)d_in[4];
    float*       outp   = (float*)d_out;

    const int n_nodes = in_sizes[0] / TILE;   // 4096
    const int n_edges = in_sizes[2] / TILE;   // 32768

    cudaFuncSetAttribute(mma_conv<false>, cudaFuncAttributeMaxDynamicSharedMemorySize, SMEM_BYTES);
    cudaFuncSetAttribute(mma_conv<true>,  cudaFuncAttributeMaxDynamicSharedMemorySize, SMEM_BYTES);

    mma_conv<false><<<148, 512, SMEM_BYTES>>>(input, w_node, nullptr, nullptr, n_nodes);
    mma_conv<true><<<148, 512, SMEM_BYTES>>>(e, w_edge, srcs, outp, n_edges);
}

// round 12
// speedup vs baseline: 1.6767x; 1.6767x over previous
#include <cuda_runtime.h>
#include <cuda_bf16.h>
#include <cstdint>
#include <math.h>

// Shapes: input [4096,32,8,8] f32 | edge_sources [32768] i32 | e [32768,32,8,8] f32
//         w_* [32,32,3,3] f32 | out [32768,32,8,8] f32
#define TILE   2048
#define NNODES 4096
__device__ float g_th[(size_t)NNODES * TILE];

typedef uint32_t u32;
typedef unsigned short u16;

// ---- smem u32-offsets ----
#define AH_U   0u
#define AL_U   6912u          // 9*32*24
#define B_U    13824u
#define B_ITEM 4800u
#define SMEM_BYTES ((13824u + 8u * 4800u) * 4u)   // 208896 B

#define MMA(dd, A0, A1, A2, A3, B0, B1)                                          \
    asm volatile("mma.sync.aligned.m16n8k16.row.col.f32.bf16.bf16.f32 "          \
                 "{%0,%1,%2,%3}, {%4,%5,%6,%7}, {%8,%9}, {%0,%1,%2,%3};"         \
                 : "+f"((dd)[0]), "+f"((dd)[1]), "+f"((dd)[2]), "+f"((dd)[3])    \
                 : "r"(A0), "r"(A1), "r"(A2), "r"(A3), "r"(B0), "r"(B1))

__device__ __forceinline__ float elu1(float v) { return v > 0.0f ? v : expm1f(v); }

__device__ __forceinline__ void split_bf16(float v, u16& h, u16& l) {
    __nv_bfloat16 hb = __float2bfloat16(v);
    __nv_bfloat16 lb = __float2bfloat16(v - __bfloat162float(hb));
    h = __bfloat16_as_ushort(hb);
    l = __bfloat16_as_ushort(lb);
}

// Warp-pair per item; warp computes 32co x 32px (its y-half).
// 3-pass bf16 hi/lo split. R9 MMA order (verified 554us). NEW: next-item pixel
// prefetch into registers issued before the MMA phase to hide LDG latency.
template <bool EDGE>
__global__ __launch_bounds__(512, 1)
void mma_conv(const float* __restrict__ x,
              const float* __restrict__ w,
              const int*   __restrict__ srcs,
              float*       __restrict__ out,
              int nitems)
{
    extern __shared__ __align__(16) u32 S[];
    const int tid  = threadIdx.x;
    const int wid  = tid >> 5;
    const int lane = tid & 31;
    const int row  = lane >> 2;
    const int quad = lane & 3;
    const int pr   = wid >> 1;
    const int nh   = wid & 1;

    // ---- one-time: weights -> A hi/lo (paired-slot layout) ----
    for (int i = tid; i < 9216; i += 512) {
        int co = i / 288, r = i - co * 288;
        int ci = r / 9,   tap = r - ci * 9;
        u16 h, l;
        split_bf16(w[i], h, l);
        int j = ci >> 1, odd = ci & 1;
        int ks = j >> 3, jq = j & 7, q = jq & 3, hh = jq >> 2;
        u32 idx = (u32)(tap * 32 + co) * 24 + ks * 8 + q * 2 + hh;
        *(u16*)((char*)S + (size_t)(AH_U + idx) * 4 + odd * 2) = h;
        *(u16*)((char*)S + (size_t)(AL_U + idx) * 4 + odd * 2) = l;
    }
    for (u32 i = tid; i < 8 * B_ITEM; i += 512) S[B_U + i] = 0;
    __syncthreads();

    u32* Bh = S + B_U + (u32)pr * B_ITEM;
    u32* Bl = Bh + 2400;
    const int t2  = tid & 63;
    const int p24 = (((t2 >> 3) + 1) * 10 + (t2 & 7) + 1) * 24;
    const int step = gridDim.x * 8;

    // ---- prologue: prefetch first item's pixels ----
    float pf[32];
    int item = blockIdx.x * 8 + pr;
    if (item < nitems) {
        const float* ei = x + (size_t)item * TILE + t2;
        #pragma unroll
        for (int j = 0; j < 32; j++) pf[j] = __ldg(ei + j * 64);
    }
    int psrc = (EDGE && item < nitems) ? __ldg(srcs + item) : 0;

    for (; item < nitems; item += step) {
        // ---- STS current item's pixels from prefetch regs ----
        #pragma unroll
        for (int j = 0; j < 16; j++) {
            u16 h0, l0, h1, l1;
            split_bf16(pf[2 * j],     h0, l0);
            split_bf16(pf[2 * j + 1], h1, l1);
            int slot = (j >> 3) * 8 + (j & 3) * 2 + ((j >> 2) & 1);
            Bh[p24 + slot] = ((u32)h1 << 16) | h0;
            Bl[p24 + slot] = ((u32)l1 << 16) | l0;
        }
        asm volatile("bar.sync %0, 64;" :: "r"(pr + 1) : "memory");

        const int src = psrc;

        // ---- issue next item's LDGs now; they drain during the MMA phase ----
        const int nitem = item + step;
        if (nitem < nitems) {
            const float* en = x + (size_t)nitem * TILE + t2;
            #pragma unroll
            for (int j = 0; j < 32; j++) pf[j] = __ldg(en + j * 64);
            if (EDGE) psrc = __ldg(srcs + nitem);
        }

        float d[2][4][4];
        #pragma unroll
        for (int m = 0; m < 2; m++)
            #pragma unroll
            for (int n = 0; n < 4; n++)
                #pragma unroll
                for (int k = 0; k < 4; k++) d[m][n][k] = 0.0f;

        #pragma unroll 1
        for (int tap = 0; tap < 9; tap++) {
            const int dy = tap / 3, dx = tap - dy * 3;
            const u32 pixb = (u32)(dy * 10 + dx + row + nh * 40) * 24;
            #pragma unroll
            for (int ks = 0; ks < 2; ks++) {
                const u32* ap = S + AH_U + (u32)tap * 768 + (u32)row * 24 + ks * 8 + quad * 2;
                uint2 h01 = *(const uint2*)(ap);
                uint2 h23 = *(const uint2*)(ap + 192);
                uint2 h45 = *(const uint2*)(ap + 384);
                uint2 h67 = *(const uint2*)(ap + 576);
                const u32* alp = ap + AL_U;
                uint2 l01 = *(const uint2*)(alp);
                uint2 l23 = *(const uint2*)(alp + 192);
                uint2 l45 = *(const uint2*)(alp + 384);
                uint2 l67 = *(const uint2*)(alp + 576);
                const u32* bp = Bh + pixb + ks * 8 + quad * 2;
                #pragma unroll
                for (int n = 0; n < 4; n++) {
                    uint2 bh = *(const uint2*)(bp + n * 240);
                    uint2 bl = *(const uint2*)(bp + n * 240 + 2400);
                    MMA(d[0][n], h01.x, h23.x, h01.y, h23.y, bh.x, bh.y);
                    MMA(d[1][n], h45.x, h67.x, h45.y, h67.y, bh.x, bh.y);
                    MMA(d[0][n], h01.x, h23.x, h01.y, h23.y, bl.x, bl.y);
                    MMA(d[1][n], h45.x, h67.x, h45.y, h67.y, bl.x, bl.y);
                    MMA(d[0][n], l01.x, l23.x, l01.y, l23.y, bh.x, bh.y);
                    MMA(d[1][n], l45.x, l67.x, l45.y, l67.y, bh.x, bh.y);
                }
            }
        }

        // ---- epilogue: co = m*16+row (+8), y = nh*4+n, x = 2quad..+1 ----
        if (EDGE) {
            const float* thp = g_th + (size_t)src * TILE;
            float* op = out + (size_t)item * TILE;
            #pragma unroll
            for (int m = 0; m < 2; m++) {
                const int co0 = m * 16 + row, co1 = co0 + 8;
                #pragma unroll
                for (int n = 0; n < 4; n++) {
                    const int pb = (nh * 4 + n) * 8 + 2 * quad;
                    float2 t0 = *(const float2*)(thp + co0 * 64 + pb);
                    float2 t1 = *(const float2*)(thp + co1 * 64 + pb);
                    *(float2*)(op + co0 * 64 + pb) =
                        make_float2(elu1(t0.x * d[m][n][0]), elu1(t0.y * d[m][n][1]));
                    *(float2*)(op + co1 * 64 + pb) =
                        make_float2(elu1(t1.x * d[m][n][2]), elu1(t1.y * d[m][n][3]));
                }
            }
        } else {
            float* op = g_th + (size_t)item * TILE;
            #pragma unroll
            for (int m = 0; m < 2; m++) {
                const int co0 = m * 16 + row, co1 = co0 + 8;
                #pragma unroll
                for (int n = 0; n < 4; n++) {
                    const int pb = (nh * 4 + n) * 8 + 2 * quad;
                    *(float2*)(op + co0 * 64 + pb) = make_float2(d[m][n][0], d[m][n][1]);
                    *(float2*)(op + co1 * 64 + pb) = make_float2(d[m][n][2], d[m][n][3]);
                }
            }
        }
        asm volatile("bar.sync %0, 64;" :: "r"(pr + 1) : "memory");
    }
}

extern "C" void kernel_launch(void* const* d_in, const int* in_sizes, int n_in,
                              void* d_out, int out_size)
{
    const float* input  = (const float*)d_in[0];
    const int*   srcs   = (const int*)  d_in[1];
    const float* e      = (const float*)d_in[2];
    const float* w_node = (const float*)d_in[3];
    const float* w_edge = (const float*)d_in[4];
    float*       outp   = (float*)d_out;

    const int n_nodes = in_sizes[0] / TILE;   // 4096
    const int n_edges = in_sizes[2] / TILE;   // 32768

    cudaFuncSetAttribute(mma_conv<false>, cudaFuncAttributeMaxDynamicSharedMemorySize, SMEM_BYTES);
    cudaFuncSetAttribute(mma_conv<true>,  cudaFuncAttributeMaxDynamicSharedMemorySize, SMEM_BYTES);

    mma_conv<false><<<148, 512, SMEM_BYTES>>>(input, w_node, nullptr, nullptr, n_nodes);
    mma_conv<true><<<148, 512, SMEM_BYTES>>>(e, w_edge, srcs, outp, n_edges);
}

// round 13
// speedup vs baseline: 2.2058x; 1.3156x over previous
#include <cuda_runtime.h>
#include <cuda_fp16.h>
#include <cstdint>
#include <math.h>

// Shapes: input [4096,32,8,8] f32 | edge_sources [32768] i32 | e [32768,32,8,8] f32
//         w_* [32,32,3,3] f32 | out [32768,32,8,8] f32
#define TILE   2048
#define NNODES 4096
__device__ float g_th[(size_t)NNODES * TILE];

typedef uint32_t u32;
typedef unsigned short u16;

// ---- smem u32-offsets ----
// A: [tap9][co32][24 slots] u32 (hi), then lo region. slot = ks*8 + quad*2 + hh
#define AH_U   0u
#define AL_U   6912u          // 9*32*24
// B per item: [100 pix][24 slots] u32, fp16 e (hi only)
#define B_U    13824u
#define B_ITEM 2400u
#define SMEM_BYTES ((13824u + 8u * 2400u) * 4u)   // 132096 B

#define MMA(dd, A0, A1, A2, A3, B0, B1)                                          \
    asm volatile("mma.sync.aligned.m16n8k16.row.col.f32.f16.f16.f32 "            \
                 "{%0,%1,%2,%3}, {%4,%5,%6,%7}, {%8,%9}, {%0,%1,%2,%3};"         \
                 : "+f"((dd)[0]), "+f"((dd)[1]), "+f"((dd)[2]), "+f"((dd)[3])    \
                 : "r"(A0), "r"(A1), "r"(A2), "r"(A3), "r"(B0), "r"(B1))

__device__ __forceinline__ float elu1(float v) { return v > 0.0f ? v : expm1f(v); }

__device__ __forceinline__ void split_fp16(float v, u16& h, u16& l) {
    __half hb = __float2half_rn(v);
    __half lb = __float2half_rn(v - __half2float(hb));
    h = __half_as_ushort(hb);
    l = __half_as_ushort(lb);
}
__device__ __forceinline__ u16 to_fp16(float v) {
    return __half_as_ushort(__float2half_rn(v));
}

// Warp-pair per item; warp computes 32co x 32px (its y-half).
// fp16 2-pass: w = wh + wl (exact), e rounded once to fp16.
// R11 structure: next-item register prefetch, R9 MMA order, stride-24 layouts.
template <bool EDGE>
__global__ __launch_bounds__(512, 1)
void mma_conv(const float* __restrict__ x,
              const float* __restrict__ w,
              const int*   __restrict__ srcs,
              float*       __restrict__ out,
              int nitems)
{
    extern __shared__ __align__(16) u32 S[];
    const int tid  = threadIdx.x;
    const int wid  = tid >> 5;
    const int lane = tid & 31;
    const int row  = lane >> 2;
    const int quad = lane & 3;
    const int pr   = wid >> 1;
    const int nh   = wid & 1;

    // ---- one-time: weights -> A hi/lo (paired-slot layout) ----
    for (int i = tid; i < 9216; i += 512) {
        int co = i / 288, r = i - co * 288;
        int ci = r / 9,   tap = r - ci * 9;
        u16 h, l;
        split_fp16(w[i], h, l);
        int j = ci >> 1, odd = ci & 1;
        int ks = j >> 3, jq = j & 7, q = jq & 3, hh = jq >> 2;
        u32 idx = (u32)(tap * 32 + co) * 24 + ks * 8 + q * 2 + hh;
        *(u16*)((char*)S + (size_t)(AH_U + idx) * 4 + odd * 2) = h;
        *(u16*)((char*)S + (size_t)(AL_U + idx) * 4 + odd * 2) = l;
    }
    for (u32 i = tid; i < 8 * B_ITEM; i += 512) S[B_U + i] = 0;
    __syncthreads();

    u32* Bh = S + B_U + (u32)pr * B_ITEM;
    const int t2  = tid & 63;
    const int p24 = (((t2 >> 3) + 1) * 10 + (t2 & 7) + 1) * 24;
    const int step = gridDim.x * 8;

    // ---- prologue: prefetch first item's pixels ----
    float pf[32];
    int item = blockIdx.x * 8 + pr;
    if (item < nitems) {
        const float* ei = x + (size_t)item * TILE + t2;
        #pragma unroll
        for (int j = 0; j < 32; j++) pf[j] = __ldg(ei + j * 64);
    }
    int psrc = (EDGE && item < nitems) ? __ldg(srcs + item) : 0;

    for (; item < nitems; item += step) {
        // ---- STS current item's pixels (fp16, hi only) ----
        #pragma unroll
        for (int j = 0; j < 16; j++) {
            u16 h0 = to_fp16(pf[2 * j]);
            u16 h1 = to_fp16(pf[2 * j + 1]);
            int slot = (j >> 3) * 8 + (j & 3) * 2 + ((j >> 2) & 1);
            Bh[p24 + slot] = ((u32)h1 << 16) | h0;
        }
        asm volatile("bar.sync %0, 64;" :: "r"(pr + 1) : "memory");

        const int src = psrc;

        // ---- issue next item's LDGs; they drain under the MMA phase ----
        const int nitem = item + step;
        if (nitem < nitems) {
            const float* en = x + (size_t)nitem * TILE + t2;
            #pragma unroll
            for (int j = 0; j < 32; j++) pf[j] = __ldg(en + j * 64);
            if (EDGE) psrc = __ldg(srcs + nitem);
        }

        float d[2][4][4];
        #pragma unroll
        for (int m = 0; m < 2; m++)
            #pragma unroll
            for (int n = 0; n < 4; n++)
                #pragma unroll
                for (int k = 0; k < 4; k++) d[m][n][k] = 0.0f;

        #pragma unroll 1
        for (int tap = 0; tap < 9; tap++) {
            const int dy = tap / 3, dx = tap - dy * 3;
            const u32 pixb = (u32)(dy * 10 + dx + row + nh * 40) * 24;
            #pragma unroll
            for (int ks = 0; ks < 2; ks++) {
                const u32* ap = S + AH_U + (u32)tap * 768 + (u32)row * 24 + ks * 8 + quad * 2;
                uint2 h01 = *(const uint2*)(ap);
                uint2 h23 = *(const uint2*)(ap + 192);
                uint2 h45 = *(const uint2*)(ap + 384);
                uint2 h67 = *(const uint2*)(ap + 576);
                const u32* alp = ap + AL_U;
                uint2 l01 = *(const uint2*)(alp);
                uint2 l23 = *(const uint2*)(alp + 192);
                uint2 l45 = *(const uint2*)(alp + 384);
                uint2 l67 = *(const uint2*)(alp + 576);
                const u32* bp = Bh + pixb + ks * 8 + quad * 2;
                #pragma unroll
                for (int n = 0; n < 4; n++) {
                    uint2 bh = *(const uint2*)(bp + n * 240);
                    MMA(d[0][n], h01.x, h23.x, h01.y, h23.y, bh.x, bh.y);  // wh*e
                    MMA(d[1][n], h45.x, h67.x, h45.y, h67.y, bh.x, bh.y);
                    MMA(d[0][n], l01.x, l23.x, l01.y, l23.y, bh.x, bh.y);  // wl*e
                    MMA(d[1][n], l45.x, l67.x, l45.y, l67.y, bh.x, bh.y);
                }
            }
        }

        // ---- epilogue: co = m*16+row (+8), y = nh*4+n, x = 2quad..+1 ----
        if (EDGE) {
            const float* thp = g_th + (size_t)src * TILE;
            float* op = out + (size_t)item * TILE;
            #pragma unroll
            for (int m = 0; m < 2; m++) {
                const int co0 = m * 16 + row, co1 = co0 + 8;
                #pragma unroll
                for (int n = 0; n < 4; n++) {
                    const int pb = (nh * 4 + n) * 8 + 2 * quad;
                    float2 t0 = *(const float2*)(thp + co0 * 64 + pb);
                    float2 t1 = *(const float2*)(thp + co1 * 64 + pb);
                    *(float2*)(op + co0 * 64 + pb) =
                        make_float2(elu1(t0.x * d[m][n][0]), elu1(t0.y * d[m][n][1]));
                    *(float2*)(op + co1 * 64 + pb) =
                        make_float2(elu1(t1.x * d[m][n][2]), elu1(t1.y * d[m][n][3]));
                }
            }
        } else {
            float* op = g_th + (size_t)item * TILE;
            #pragma unroll
            for (int m = 0; m < 2; m++) {
                const int co0 = m * 16 + row, co1 = co0 + 8;
                #pragma unroll
                for (int n = 0; n < 4; n++) {
                    const int pb = (nh * 4 + n) * 8 + 2 * quad;
                    *(float2*)(op + co0 * 64 + pb) = make_float2(d[m][n][0], d[m][n][1]);
                    *(float2*)(op + co1 * 64 + pb) = make_float2(d[m][n][2], d[m][n][3]);
                }
            }
        }
        asm volatile("bar.sync %0, 64;" :: "r"(pr + 1) : "memory");
    }
}

extern "C" void kernel_launch(void* const* d_in, const int* in_sizes, int n_in,
                              void* d_out, int out_size)
{
    const float* input  = (const float*)d_in[0];
    const int*   srcs   = (const int*)  d_in[1];
    const float* e      = (const float*)d_in[2];
    const float* w_node = (const float*)d_in[3];
    const float* w_edge = (const float*)d_in[4];
    float*       outp   = (float*)d_out;

    const int n_nodes = in_sizes[0] / TILE;   // 4096
    const int n_edges = in_sizes[2] / TILE;   // 32768

    cudaFuncSetAttribute(mma_conv<false>, cudaFuncAttributeMaxDynamicSharedMemorySize, SMEM_BYTES);
    cudaFuncSetAttribute(mma_conv<true>,  cudaFuncAttributeMaxDynamicSharedMemorySize, SMEM_BYTES);

    mma_conv<false><<<148, 512, SMEM_BYTES>>>(input, w_node, nullptr, nullptr, n_nodes);
    mma_conv<true><<<148, 512, SMEM_BYTES>>>(e, w_edge, srcs, outp, n_edges);
}

// round 15
// speedup vs baseline: 2.6362x; 1.1951x over previous
#include <cuda_runtime.h>
#include <cuda_fp16.h>
#include <cstdint>
#include <math.h>

// Shapes: input [4096,32,8,8] f32 | edge_sources [32768] i32 | e [32768,32,8,8] f32
//         w_* [32,32,3,3] f32 | out [32768,32,8,8] f32
#define TILE   2048
#define NNODES 4096
__device__ float g_th[(size_t)NNODES * TILE];

typedef uint32_t u32;
typedef unsigned short u16;

// ---- smem u32 layout ----
// A hi: [9 tap][32 co][20 u32] (u32 j = ciPair j; j0-7 ks0, j8-15 ks1; 4 pad)
// A lo: same at +5760 u32.  B: [8 items][100 pix][20 u32].
#define AL_U     5760u
#define B_U      11520u
#define B_ITEM   2000u
#define SMEM_BYTES ((11520u + 8u * 2000u) * 4u)   // 110080 B
#define A_BYTES  46080u

#define MMA(dd, A0, A1, A2, A3, B0, B1)                                          \
    asm volatile("mma.sync.aligned.m16n8k16.row.col.f32.f16.f16.f32 "            \
                 "{%0,%1,%2,%3}, {%4,%5,%6,%7}, {%8,%9}, {%0,%1,%2,%3};"         \
                 : "+f"((dd)[0]), "+f"((dd)[1]), "+f"((dd)[2]), "+f"((dd)[3])    \
                 : "r"(A0), "r"(A1), "r"(A2), "r"(A3), "r"(B0), "r"(B1))

#define LDSM4(r0, r1, r2, r3, a)                                                 \
    asm volatile("ldmatrix.sync.aligned.m8n8.x4.shared.b16 {%0,%1,%2,%3}, [%4];" \
                 : "=r"(r0), "=r"(r1), "=r"(r2), "=r"(r3) : "r"(a))

__device__ __forceinline__ float elu1(float v) { return v > 0.0f ? v : expm1f(v); }

__device__ __forceinline__ void split_fp16(float v, u16& h, u16& l) {
    __half hb = __float2half_rn(v);
    __half lb = __float2half_rn(v - __half2float(hb));
    h = __half_as_ushort(hb);
    l = __half_as_ushort(lb);
}
__device__ __forceinline__ u16 to_fp16(float v) {
    return __half_as_ushort(__float2half_rn(v));
}

// Warp-pair per item; warp computes 32co x 32px (its y-half).
// fp16 2-pass (w exact hi+lo, e rounded once). ldmatrix fragment loads
// (non-trans for BOTH A and B: B rows [n][k] are already col-major operand).
template <bool EDGE>
__global__ __launch_bounds__(512, 1)
void mma_conv(const float* __restrict__ x,
              const float* __restrict__ w,
              const int*   __restrict__ srcs,
              float*       __restrict__ out,
              int nitems)
{
    extern __shared__ __align__(16) u32 S[];
    const int tid  = threadIdx.x;
    const int wid  = tid >> 5;
    const int lane = tid & 31;
    const int row  = lane >> 2;
    const int quad = lane & 3;
    const int pr   = wid >> 1;
    const int nh   = wid & 1;

    // ---- one-time: weights -> A hi/lo ([tap][co][20u32], j = ci>>1) ----
    for (int i = tid; i < 9216; i += 512) {
        int co = i / 288, r = i - co * 288;
        int ci = r / 9,   tap = r - ci * 9;
        u16 h, l;
        split_fp16(w[i], h, l);
        u32 idx = (u32)(tap * 32 + co) * 20 + (ci >> 1);
        int odd = ci & 1;
        *(u16*)((char*)S + (size_t)idx * 4 + odd * 2) = h;
        *(u16*)((char*)S + (size_t)(AL_U + idx) * 4 + odd * 2) = l;
    }
    for (u32 i = tid; i < 8 * B_ITEM; i += 512) S[B_U + i] = 0;
    __syncthreads();

    const u32 sbase  = (u32)__cvta_generic_to_shared(S);
    // A: lanes 0-15 -> co rows 0-15 (+0B: k0-7), lanes 16-31 -> same rows +16B (k8-15)
    const u32 a_lane = sbase + (u32)((lane & 15) * 80 + (lane >> 4) * 16);
    // B: lane&7 -> x, bit3 -> k-half (+16B), bit4 -> y+1 (+10 pixels)
    const u32 b_lane = sbase + A_BYTES + (u32)pr * 8000u
                     + (u32)(((lane & 7) + (lane >> 4) * 10 + nh * 40) * 80
                             + ((lane >> 3) & 1) * 16);

    u32* Bh = S + B_U + (u32)pr * B_ITEM;
    const int t2  = tid & 63;
    const int p20 = (((t2 >> 3) + 1) * 10 + (t2 & 7) + 1) * 20;
    const int step = gridDim.x * 8;

    // ---- prologue: prefetch first item's pixels ----
    float pf[32];
    int item = blockIdx.x * 8 + pr;
    if (item < nitems) {
        const float* ei = x + (size_t)item * TILE + t2;
        #pragma unroll
        for (int j = 0; j < 32; j++) pf[j] = __ldg(ei + j * 64);
    }
    int psrc = (EDGE && item < nitems) ? __ldg(srcs + item) : 0;

    for (; item < nitems; item += step) {
        // ---- STS current item's pixels (fp16, j = ciPair contiguous) ----
        #pragma unroll
        for (int j = 0; j < 16; j++) {
            u16 h0 = to_fp16(pf[2 * j]);
            u16 h1 = to_fp16(pf[2 * j + 1]);
            Bh[p20 + j] = ((u32)h1 << 16) | h0;
        }
        asm volatile("bar.sync %0, 64;" :: "r"(pr + 1) : "memory");

        const int src = psrc;

        // ---- issue next item's LDGs; they drain under the MMA phase ----
        const int nitem = item + step;
        if (nitem < nitems) {
            const float* en = x + (size_t)nitem * TILE + t2;
            #pragma unroll
            for (int j = 0; j < 32; j++) pf[j] = __ldg(en + j * 64);
            if (EDGE) psrc = __ldg(srcs + nitem);
        }

        float d[2][4][4];
        #pragma unroll
        for (int m = 0; m < 2; m++)
            #pragma unroll
            for (int n = 0; n < 4; n++)
                #pragma unroll
                for (int k = 0; k < 4; k++) d[m][n][k] = 0.0f;

        #pragma unroll 1
        for (int tap = 0; tap < 9; tap++) {
            const int dy = tap / 3, dx = tap - dy * 3;
            const u32 boff = b_lane + (u32)((dy * 10 + dx) * 80);
            const u32 aoff = a_lane + (u32)(tap * 2560);
            #pragma unroll
            for (int ks = 0; ks < 2; ks++) {
                const u32 ko = (u32)(ks * 32);
                u32 ah0, ah1, ah2, ah3, ah4, ah5, ah6, ah7;
                u32 al0, al1, al2, al3, al4, al5, al6, al7;
                u32 b0, b1, b2, b3, b4, b5, b6, b7;
                LDSM4(ah0, ah1, ah2, ah3, aoff + ko);            // co 0-15
                LDSM4(ah4, ah5, ah6, ah7, aoff + ko + 1280);     // co 16-31
                LDSM4(al0, al1, al2, al3, aoff + ko + 23040);
                LDSM4(al4, al5, al6, al7, aoff + ko + 23040 + 1280);
                LDSM4(b0, b1, b2, b3, boff + ko);                // n-tiles 0,1 (y+0,y+1)
                LDSM4(b4, b5, b6, b7, boff + ko + 1600);         // n-tiles 2,3 (y+2,y+3)
                MMA(d[0][0], ah0, ah1, ah2, ah3, b0, b1);
                MMA(d[1][0], ah4, ah5, ah6, ah7, b0, b1);
                MMA(d[0][0], al0, al1, al2, al3, b0, b1);
                MMA(d[1][0], al4, al5, al6, al7, b0, b1);
                MMA(d[0][1], ah0, ah1, ah2, ah3, b2, b3);
                MMA(d[1][1], ah4, ah5, ah6, ah7, b2, b3);
                MMA(d[0][1], al0, al1, al2, al3, b2, b3);
                MMA(d[1][1], al4, al5, al6, al7, b2, b3);
                MMA(d[0][2], ah0, ah1, ah2, ah3, b4, b5);
                MMA(d[1][2], ah4, ah5, ah6, ah7, b4, b5);
                MMA(d[0][2], al0, al1, al2, al3, b4, b5);
                MMA(d[1][2], al4, al5, al6, al7, b4, b5);
                MMA(d[0][3], ah0, ah1, ah2, ah3, b6, b7);
                MMA(d[1][3], ah4, ah5, ah6, ah7, b6, b7);
                MMA(d[0][3], al0, al1, al2, al3, b6, b7);
                MMA(d[1][3], al4, al5, al6, al7, b6, b7);
            }
        }

        // ---- epilogue: co = m*16+row (+8), y = nh*4+n, x = 2quad..+1 ----
        if (EDGE) {
            const float* thp = g_th + (size_t)src * TILE;
            float* op = out + (size_t)item * TILE;
            #pragma unroll
            for (int m = 0; m < 2; m++) {
                const int co0 = m * 16 + row, co1 = co0 + 8;
                #pragma unroll
                for (int n = 0; n < 4; n++) {
                    const int pb = (nh * 4 + n) * 8 + 2 * quad;
                    float2 t0 = *(const float2*)(thp + co0 * 64 + pb);
                    float2 t1 = *(const float2*)(thp + co1 * 64 + pb);
                    *(float2*)(op + co0 * 64 + pb) =
                        make_float2(elu1(t0.x * d[m][n][0]), elu1(t0.y * d[m][n][1]));
                    *(float2*)(op + co1 * 64 + pb) =
                        make_float2(elu1(t1.x * d[m][n][2]), elu1(t1.y * d[m][n][3]));
                }
            }
        } else {
            float* op = g_th + (size_t)item * TILE;
            #pragma unroll
            for (int m = 0; m < 2; m++) {
                const int co0 = m * 16 + row, co1 = co0 + 8;
                #pragma unroll
                for (int n = 0; n < 4; n++) {
                    const int pb = (nh * 4 + n) * 8 + 2 * quad;
                    *(float2*)(op + co0 * 64 + pb) = make_float2(d[m][n][0], d[m][n][1]);
                    *(float2*)(op + co1 * 64 + pb) = make_float2(d[m][n][2], d[m][n][3]);
                }
            }
        }
        asm volatile("bar.sync %0, 64;" :: "r"(pr + 1) : "memory");
    }
}

extern "C" void kernel_launch(void* const* d_in, const int* in_sizes, int n_in,
                              void* d_out, int out_size)
{
    const float* input  = (const float*)d_in[0];
    const int*   srcs   = (const int*)  d_in[1];
    const float* e      = (const float*)d_in[2];
    const float* w_node = (const float*)d_in[3];
    const float* w_edge = (const float*)d_in[4];
    float*       outp   = (float*)d_out;

    const int n_nodes = in_sizes[0] / TILE;   // 4096
    const int n_edges = in_sizes[2] / TILE;   // 32768

    cudaFuncSetAttribute(mma_conv<false>, cudaFuncAttributeMaxDynamicSharedMemorySize, SMEM_BYTES);
    cudaFuncSetAttribute(mma_conv<true>,  cudaFuncAttributeMaxDynamicSharedMemorySize, SMEM_BYTES);

    mma_conv<false><<<148, 512, SMEM_BYTES>>>(input, w_node, nullptr, nullptr, n_nodes);
    mma_conv<true><<<148, 512, SMEM_BYTES>>>(e, w_edge, srcs, outp, n_edges);
}

// round 17
// speedup vs baseline: 3.2660x; 1.2389x over previous
#include <cuda_runtime.h>
#include <cuda_fp16.h>
#include <cstdint>
#include <math.h>

// Shapes: input [4096,32,8,8] f32 | edge_sources [32768] i32 | e [32768,32,8,8] f32
//         w_* [32,32,3,3] f32 | out [32768,32,8,8] f32
#define TILE   2048
#define NNODES 4096
__device__ float g_th[(size_t)NNODES * TILE];

typedef uint32_t u32;
typedef unsigned short u16;

// ---- smem u32 layout ----
// A: [9 tap][32 co][20 u32] (u32 j = ciPair j; j0-7 ks0, j8-15 ks1; 4 pad)
// B: [8 items][100 pix][20 u32].
#define B_U      5760u
#define B_ITEM   2000u
#define SMEM_BYTES ((5760u + 8u * 2000u) * 4u)   // 87040 B
#define A_BYTES  23040u

#define MMA(dd, A0, A1, A2, A3, B0, B1)                                          \
    asm volatile("mma.sync.aligned.m16n8k16.row.col.f32.f16.f16.f32 "            \
                 "{%0,%1,%2,%3}, {%4,%5,%6,%7}, {%8,%9}, {%0,%1,%2,%3};"         \
                 : "+f"((dd)[0]), "+f"((dd)[1]), "+f"((dd)[2]), "+f"((dd)[3])    \
                 : "r"(A0), "r"(A1), "r"(A2), "r"(A3), "r"(B0), "r"(B1))

#define LDSM4(r0, r1, r2, r3, a)                                                 \
    asm volatile("ldmatrix.sync.aligned.m8n8.x4.shared.b16 {%0,%1,%2,%3}, [%4];" \
                 : "=r"(r0), "=r"(r1), "=r"(r2), "=r"(r3) : "r"(a))

__device__ __forceinline__ float elu1(float v) { return v > 0.0f ? v : expm1f(v); }

__device__ __forceinline__ u16 to_fp16(float v) {
    return __half_as_ushort(__float2half_rn(v));
}

// Warp-pair per item; warp computes 32co x 32px (its y-half).
// Plain fp16 (both w and e rounded once; rel_err ~4e-4 < 1e-3).
// ldmatrix fragment loads, next-item register prefetch.
template <bool EDGE>
__global__ __launch_bounds__(512, 1)
void mma_conv(const float* __restrict__ x,
              const float* __restrict__ w,
              const int*   __restrict__ srcs,
              float*       __restrict__ out,
              int nitems)
{
    extern __shared__ __align__(16) u32 S[];
    const int tid  = threadIdx.x;
    const int wid  = tid >> 5;
    const int lane = tid & 31;
    const int row  = lane >> 2;
    const int quad = lane & 3;
    const int pr   = wid >> 1;
    const int nh   = wid & 1;

    // ---- one-time: weights -> A ([tap][co][20u32], j = ci>>1) ----
    for (int i = tid; i < 9216; i += 512) {
        int co = i / 288, r = i - co * 288;
        int ci = r / 9,   tap = r - ci * 9;
        u32 idx = (u32)(tap * 32 + co) * 20 + (ci >> 1);
        *(u16*)((char*)S + (size_t)idx * 4 + (ci & 1) * 2) = to_fp16(w[i]);
    }
    for (u32 i = tid; i < 8 * B_ITEM; i += 512) S[B_U + i] = 0;
    __syncthreads();

    const u32 sbase  = (u32)__cvta_generic_to_shared(S);
    // A: lanes 0-15 -> co rows (+0B k0-7), lanes 16-31 -> +16B (k8-15)
    const u32 a_lane = sbase + (u32)((lane & 15) * 80 + (lane >> 4) * 16);
    // B: lane&7 -> x, bit3 -> k-half (+16B), bit4 -> y+1 (+10 pixels)
    const u32 b_lane = sbase + A_BYTES + (u32)pr * 8000u
                     + (u32)(((lane & 7) + (lane >> 4) * 10 + nh * 40) * 80
                             + ((lane >> 3) & 1) * 16);

    u32* Bh = S + B_U + (u32)pr * B_ITEM;
    const int t2  = tid & 63;
    const int p20 = (((t2 >> 3) + 1) * 10 + (t2 & 7) + 1) * 20;
    const int step = gridDim.x * 8;

    // ---- prologue: prefetch first item's pixels ----
    float pf[32];
    int item = blockIdx.x * 8 + pr;
    if (item < nitems) {
        const float* ei = x + (size_t)item * TILE + t2;
        #pragma unroll
        for (int j = 0; j < 32; j++) pf[j] = __ldg(ei + j * 64);
    }
    int psrc = (EDGE && item < nitems) ? __ldg(srcs + item) : 0;

    for (; item < nitems; item += step) {
        // ---- STS current item's pixels (fp16, j = ciPair contiguous) ----
        #pragma unroll
        for (int j = 0; j < 16; j++) {
            u16 h0 = to_fp16(pf[2 * j]);
            u16 h1 = to_fp16(pf[2 * j + 1]);
            Bh[p20 + j] = ((u32)h1 << 16) | h0;
        }
        asm volatile("bar.sync %0, 64;" :: "r"(pr + 1) : "memory");

        const int src = psrc;

        // ---- issue next item's LDGs; they drain under the MMA phase ----
        const int nitem = item + step;
        if (nitem < nitems) {
            const float* en = x + (size_t)nitem * TILE + t2;
            #pragma unroll
            for (int j = 0; j < 32; j++) pf[j] = __ldg(en + j * 64);
            if (EDGE) psrc = __ldg(srcs + nitem);
        }

        float d[2][4][4];
        #pragma unroll
        for (int m = 0; m < 2; m++)
            #pragma unroll
            for (int n = 0; n < 4; n++)
                #pragma unroll
                for (int k = 0; k < 4; k++) d[m][n][k] = 0.0f;

        #pragma unroll 1
        for (int tap = 0; tap < 9; tap++) {
            const int dy = tap / 3, dx = tap - dy * 3;
            const u32 boff = b_lane + (u32)((dy * 10 + dx) * 80);
            const u32 aoff = a_lane + (u32)(tap * 2560);
            #pragma unroll
            for (int ks = 0; ks < 2; ks++) {
                const u32 ko = (u32)(ks * 32);
                u32 ah0, ah1, ah2, ah3, ah4, ah5, ah6, ah7;
                u32 b0, b1, b2, b3, b4, b5, b6, b7;
                LDSM4(ah0, ah1, ah2, ah3, aoff + ko);            // co 0-15
                LDSM4(ah4, ah5, ah6, ah7, aoff + ko + 1280);     // co 16-31
                LDSM4(b0, b1, b2, b3, boff + ko);                // n-tiles 0,1
                LDSM4(b4, b5, b6, b7, boff + ko + 1600);         // n-tiles 2,3
                MMA(d[0][0], ah0, ah1, ah2, ah3, b0, b1);
                MMA(d[1][0], ah4, ah5, ah6, ah7, b0, b1);
                MMA(d[0][1], ah0, ah1, ah2, ah3, b2, b3);
                MMA(d[1][1], ah4, ah5, ah6, ah7, b2, b3);
                MMA(d[0][2], ah0, ah1, ah2, ah3, b4, b5);
                MMA(d[1][2], ah4, ah5, ah6, ah7, b4, b5);
                MMA(d[0][3], ah0, ah1, ah2, ah3, b6, b7);
                MMA(d[1][3], ah4, ah5, ah6, ah7, b6, b7);
            }
        }

        // ---- epilogue: co = m*16+row (+8), y = nh*4+n, x = 2quad..+1 ----
        if (EDGE) {
            const float* thp = g_th + (size_t)src * TILE;
            float* op = out + (size_t)item * TILE;
            #pragma unroll
            for (int m = 0; m < 2; m++) {
                const int co0 = m * 16 + row, co1 = co0 + 8;
                #pragma unroll
                for (int n = 0; n < 4; n++) {
                    const int pb = (nh * 4 + n) * 8 + 2 * quad;
                    float2 t0 = *(const float2*)(thp + co0 * 64 + pb);
                    float2 t1 = *(const float2*)(thp + co1 * 64 + pb);
                    *(float2*)(op + co0 * 64 + pb) =
                        make_float2(elu1(t0.x * d[m][n][0]), elu1(t0.y * d[m][n][1]));
                    *(float2*)(op + co1 * 64 + pb) =
                        make_float2(elu1(t1.x * d[m][n][2]), elu1(t1.y * d[m][n][3]));
                }
            }
        } else {
            float* op = g_th + (size_t)item * TILE;
            #pragma unroll
            for (int m = 0; m < 2; m++) {
                const int co0 = m * 16 + row, co1 = co0 + 8;
                #pragma unroll
                for (int n = 0; n < 4; n++) {
                    const int pb = (nh * 4 + n) * 8 + 2 * quad;
                    *(float2*)(op + co0 * 64 + pb) = make_float2(d[m][n][0], d[m][n][1]);
                    *(float2*)(op + co1 * 64 + pb) = make_float2(d[m][n][2], d[m][n][3]);
                }
            }
        }
        asm volatile("bar.sync %0, 64;" :: "r"(pr + 1) : "memory");
    }
}

extern "C" void kernel_launch(void* const* d_in, const int* in_sizes, int n_in,
                              void* d_out, int out_size)
{
    const float* input  = (const float*)d_in[0];
    const int*   srcs   = (const int*)  d_in[1];
    const float* e      = (const float*)d_in[2];
    const float* w_node = (const float*)d_in[3];
    const float* w_edge = (const float*)d_in[4];
    float*       outp   = (float*)d_out;

    const int n_nodes = in_sizes[0] / TILE;   // 4096
    const int n_edges = in_sizes[2] / TILE;   // 32768

    cudaFuncSetAttribute(mma_conv<false>, cudaFuncAttributeMaxDynamicSharedMemorySize, SMEM_BYTES);
    cudaFuncSetAttribute(mma_conv<true>,  cudaFuncAttributeMaxDynamicSharedMemorySize, SMEM_BYTES);

    mma_conv<false><<<148, 512, SMEM_BYTES>>>(input, w_node, nullptr, nullptr, n_nodes);
    mma_conv<true><<<148, 512, SMEM_BYTES>>>(e, w_edge, srcs, outp, n_edges);
}